// round 1
// baseline (speedup 1.0000x reference)
#include <cuda_runtime.h>
#include <cuda_bf16.h>

#define W_ 768
#define H_ 768
#define N_ 16
#define HW_ (H_ * W_)
#define BX 32
#define BY 8
#define GX_ (W_ / BX)          /* 24  */
#define GY_ (H_ / BY)          /* 96  */
#define NBLK (GX_ * GY_ * N_)  /* 36864 */

__device__ float g_partials[NBLK];

// m1 = warp(GridXY, flo1) evaluated analytically at integer pixel (ix,iy).
// GridXY is linear, so the masked bilinear sample has a closed form using only
// flo1 at (ix,iy): per-corner validity * weight, mask threshold at 0.9999.
__device__ __forceinline__ float2 eval_m1(const float* __restrict__ fx,
                                          const float* __restrict__ fy,
                                          int ix, int iy)
{
    int idx = iy * W_ + ix;
    float gx = (float)ix + __ldg(fx + idx);
    float gy = (float)iy + __ldg(fy + idx);
    float x0f = floorf(gx), y0f = floorf(gy);
    float wx1 = gx - x0f, wy1 = gy - y0f;
    float wx0 = 1.0f - wx1, wy0 = 1.0f - wy1;
    int x0 = (int)x0f, y0 = (int)y0f;
    bool vx0 = ((unsigned)x0 < (unsigned)W_);
    bool vx1 = ((unsigned)(x0 + 1) < (unsigned)W_);
    bool vy0 = ((unsigned)y0 < (unsigned)H_);
    bool vy1 = ((unsigned)(y0 + 1) < (unsigned)H_);
    float c00 = (vx0 && vy0) ? wx0 * wy0 : 0.0f;
    float c10 = (vx1 && vy0) ? wx1 * wy0 : 0.0f;
    float c01 = (vx0 && vy1) ? wx0 * wy1 : 0.0f;
    float c11 = (vx1 && vy1) ? wx1 * wy1 : 0.0f;
    float m = (c00 + c10) + (c01 + c11);
    const float invW = 1.0f / (float)(W_ - 1);
    const float invH = 1.0f / (float)(H_ - 1);
    float ox = ((c00 + c01) * (float)x0 + (c10 + c11) * (float)(x0 + 1)) * invW;
    float oy = ((c00 + c10) * (float)y0 + (c01 + c11) * (float)(y0 + 1)) * invH;
    float M = (m < 0.9999f) ? 0.0f : 1.0f;
    return make_float2(ox * M, oy * M);
}

// One direction's per-pixel diff: second warp (by flo2) of the analytic m1(flo1).
__device__ __forceinline__ float dir_diff(const float* __restrict__ f1x,
                                          const float* __restrict__ f1y,
                                          const float* __restrict__ f2x,
                                          const float* __restrict__ f2y,
                                          int px, int py, float Gx, float Gy)
{
    int idx = py * W_ + px;
    float gx = (float)px + __ldg(f2x + idx);
    float gy = (float)py + __ldg(f2y + idx);
    float x0f = floorf(gx), y0f = floorf(gy);
    float wx1 = gx - x0f, wy1 = gy - y0f;
    float wx0 = 1.0f - wx1, wy0 = 1.0f - wy1;
    int x0 = (int)x0f, y0 = (int)y0f;
    bool vx0 = ((unsigned)x0 < (unsigned)W_);
    bool vx1 = ((unsigned)(x0 + 1) < (unsigned)W_);
    bool vy0 = ((unsigned)y0 < (unsigned)H_);
    bool vy1 = ((unsigned)(y0 + 1) < (unsigned)H_);
    float w00 = wx0 * wy0, w10 = wx1 * wy0, w01 = wx0 * wy1, w11 = wx1 * wy1;

    float mask = 0.0f, mx = 0.0f, my = 0.0f;
    if (vx0 && vy0) {
        float2 v = eval_m1(f1x, f1y, x0, y0);
        mask += w00; mx += w00 * v.x; my += w00 * v.y;
    }
    if (vx1 && vy0) {
        float2 v = eval_m1(f1x, f1y, x0 + 1, y0);
        mask += w10; mx += w10 * v.x; my += w10 * v.y;
    }
    if (vx0 && vy1) {
        float2 v = eval_m1(f1x, f1y, x0, y0 + 1);
        mask += w01; mx += w01 * v.x; my += w01 * v.y;
    }
    if (vx1 && vy1) {
        float2 v = eval_m1(f1x, f1y, x0 + 1, y0 + 1);
        mask += w11; mx += w11 * v.x; my += w11 * v.y;
    }
    float M = (mask < 0.9999f) ? 0.0f : 1.0f;
    mx *= M; my *= M;
    float dx = Gx - mx, dy = Gy - my;
    return sqrtf(dx * dx + dy * dy + 1.0e-6f);  // EPS^2 = 1e-6
}

__global__ __launch_bounds__(BX * BY)
void fused_cycle_kernel(const float* __restrict__ A, const float* __restrict__ B)
{
    int px = blockIdx.x * BX + threadIdx.x;
    int py = blockIdx.y * BY + threadIdx.y;
    int n  = blockIdx.z;

    const float* Ax = A + (size_t)n * 2 * HW_;
    const float* Ay = Ax + HW_;
    const float* Bx = B + (size_t)n * 2 * HW_;
    const float* By = Bx + HW_;

    const float invW = 1.0f / (float)(W_ - 1);
    const float invH = 1.0f / (float)(H_ - 1);
    float Gx = (float)px * invW;
    float Gy = (float)py * invH;

    // ABA: m=warp(Grid, A) then warp(m, B)  -> f1=A, f2=B
    // BAB: f1=B, f2=A
    float s = dir_diff(Ax, Ay, Bx, By, px, py, Gx, Gy)
            + dir_diff(Bx, By, Ax, Ay, px, py, Gx, Gy);

    // Block reduction (256 threads = 8 warps)
    int lane = threadIdx.y * BX + threadIdx.x;
    #pragma unroll
    for (int o = 16; o > 0; o >>= 1)
        s += __shfl_down_sync(0xffffffffu, s, o);
    __shared__ float sh[(BX * BY) / 32];
    if ((lane & 31) == 0) sh[lane >> 5] = s;
    __syncthreads();
    if (lane < 8) {
        float v = sh[lane];
        #pragma unroll
        for (int o = 4; o > 0; o >>= 1)
            v += __shfl_down_sync(0x000000ffu, v, o);
        if (lane == 0) {
            int bid = blockIdx.x + GX_ * (blockIdx.y + GY_ * blockIdx.z);
            g_partials[bid] = v;
        }
    }
}

__global__ void final_reduce_kernel(float* __restrict__ out)
{
    __shared__ double sh[256];
    int t = threadIdx.x;
    double s = 0.0;
    for (int i = t; i < NBLK; i += 256)
        s += (double)g_partials[i];
    sh[t] = s;
    __syncthreads();
    #pragma unroll
    for (int o = 128; o > 0; o >>= 1) {
        if (t < o) sh[t] += sh[t + o];
        __syncthreads();
    }
    if (t == 0)
        out[0] = (float)(sh[0] / ((double)N_ * (double)HW_));
}

extern "C" void kernel_launch(void* const* d_in, const int* in_sizes, int n_in,
                              void* d_out, int out_size)
{
    const float* A = (const float*)d_in[0];  // UV_AtoB
    const float* B = (const float*)d_in[1];  // UV_BtoA
    dim3 block(BX, BY);
    dim3 grid(GX_, GY_, N_);
    fused_cycle_kernel<<<grid, block>>>(A, B);
    final_reduce_kernel<<<1, 256>>>((float*)d_out);
}